// round 12
// baseline (speedup 1.0000x reference)
#include <cuda_runtime.h>
#include <cuda_fp16.h>
#include <cstdint>

// ---------------------------------------------------------------------------
// GAT layer. N=8192, IN_F=512, OUT_F=256.
// out = NEG * (colsum(h) - (adj>0) @ h),  h = x @ W, NEG = -9e15.
// R12: R7 GAT kernel (measured best: 129.5us) with A-staging split into two
// half-loads (16-reg live window -> no spills). Tile 64x256, split-K(2),
// warp 32x64, B double-buffered cp.async. 5 launches.
// ---------------------------------------------------------------------------

#define NROWS   8192
#define IN_F    512
#define OUT_F   256
#define NEGC    (-9.0e15f)

// Static scratch
__device__ unsigned short g_Bh[(size_t)OUT_F * NROWS];   // h^T fp16 [k][j]
__device__ unsigned short g_W16[2 * OUT_F * IN_F];       // W^T fp16 limbs [limb][n][k]
__device__ float          g_Sp[64 * OUT_F];              // per-j-tile colsum partials
__device__ float          g_S[OUT_F];                    // colsum(h)
__device__ float          g_P[2 * (size_t)NROWS * OUT_F];// split-K partials

// ---------------------------------------------------------------------------
// helpers
// ---------------------------------------------------------------------------
__device__ __forceinline__ uint32_t smem_to_u32(const void* p) {
    uint32_t a;
    asm("{ .reg .u64 t; cvta.to.shared.u64 t, %1; cvt.u32.u64 %0, t; }" : "=r"(a) : "l"(p));
    return a;
}
__device__ __forceinline__ void cp_async16(uint32_t dst, const void* src) {
    asm volatile("cp.async.cg.shared.global [%0], [%1], 16;" :: "r"(dst), "l"(src));
}
__device__ __forceinline__ void cp_commit() { asm volatile("cp.async.commit_group;"); }
template <int N>
__device__ __forceinline__ void cp_wait() { asm volatile("cp.async.wait_group %0;" :: "n"(N)); }

__device__ __forceinline__ void ldsm_x4(uint32_t addr, uint32_t& r0, uint32_t& r1,
                                        uint32_t& r2, uint32_t& r3) {
    asm volatile("ldmatrix.sync.aligned.m8n8.x4.shared.b16 {%0,%1,%2,%3}, [%4];"
                 : "=r"(r0), "=r"(r1), "=r"(r2), "=r"(r3) : "r"(addr));
}
__device__ __forceinline__ void mma_f16(float* c, const uint32_t* a, uint32_t b0, uint32_t b1) {
    asm volatile("mma.sync.aligned.m16n8k16.row.col.f32.f16.f16.f32 "
                 "{%0,%1,%2,%3}, {%4,%5,%6,%7}, {%8,%9}, {%0,%1,%2,%3};"
                 : "+f"(c[0]), "+f"(c[1]), "+f"(c[2]), "+f"(c[3])
                 : "r"(a[0]), "r"(a[1]), "r"(a[2]), "r"(a[3]), "r"(b0), "r"(b1));
}
__device__ __forceinline__ uint32_t swz(uint32_t row, uint32_t col) {
    return row * 128u + (col ^ ((row & 7u) * 16u));
}
__device__ __forceinline__ uint32_t packh(float a, float b) {
    return (uint32_t)__half_as_ushort(__float2half_rn(a)) |
           ((uint32_t)__half_as_ushort(__float2half_rn(b)) << 16);
}

// ---------------------------------------------------------------------------
// Kernel A: split W into fp16 hi/lo limbs, transposed: g_W16[limb][n][k]
// ---------------------------------------------------------------------------
__global__ void __launch_bounds__(256) convert_W_kernel(const float* __restrict__ W) {
    int idx = blockIdx.x * 256 + threadIdx.x;       // 131072 total
    int n = idx & 255, k = idx >> 8;
    float v = W[(size_t)k * OUT_F + n];
    __half hi = __float2half_rn(v);
    __half lo = __float2half_rn(v - __half2float(hi));
    g_W16[n * IN_F + k] = __half_as_ushort(hi);
    g_W16[OUT_F * IN_F + n * IN_F + k] = __half_as_ushort(lo);
}

// ---------------------------------------------------------------------------
// Kernel B: h = x @ W on tensor cores, fp16 2-limb x 2-limb (3 terms).
// CTA: 128 j-rows x 128 n-cols, K=512 (8 chunks of 64). Grid (2 nt, 64 jt).
// Emits g_Bh[k][j] fp16 and g_Sp[jt][k] colsum partials.
// ---------------------------------------------------------------------------
#define HKC   64
#define H_A   (128 * HKC * 2)   // 16 KB per limb tile
#define H_STG (4 * H_A)         // Ahi|Alo|Bhi|Blo = 64 KB
#define H_SMEM (2 * H_STG)      // 128 KB

struct XReg { float4 v[8]; };

__device__ __forceinline__ void h_loadx(XReg& xr, const float* __restrict__ x,
                                        int j0, int it, int tid) {
    #pragma unroll
    for (int p = 0; p < 8; p++) {
        int lin = p * 256 + tid;
        int row = lin >> 4, c4 = lin & 15;
        xr.v[p] = *(const float4*)(x + (size_t)(j0 + row) * IN_F + it * HKC + c4 * 4);
    }
}
__device__ __forceinline__ void h_stsx(const XReg& xr, char* stg, int tid) {
    #pragma unroll
    for (int p = 0; p < 8; p++) {
        int lin = p * 256 + tid;
        int row = lin >> 4, c4 = lin & 15;
        float4 v = xr.v[p];
        __half hx = __float2half_rn(v.x), hy = __float2half_rn(v.y);
        __half hz = __float2half_rn(v.z), hw = __float2half_rn(v.w);
        uint32_t o = swz((uint32_t)row, (uint32_t)(c4 * 8));
        *(uint2*)(stg + o) = make_uint2(
            (uint32_t)__half_as_ushort(hx) | ((uint32_t)__half_as_ushort(hy) << 16),
            (uint32_t)__half_as_ushort(hz) | ((uint32_t)__half_as_ushort(hw) << 16));
        *(uint2*)(stg + H_A + o) = make_uint2(
            packh(v.x - __half2float(hx), v.y - __half2float(hy)),
            packh(v.z - __half2float(hz), v.w - __half2float(hw)));
    }
}
__device__ __forceinline__ void h_cpB(uint32_t stg, int n0, int it, int tid) {
    #pragma unroll
    for (int limb = 0; limb < 2; limb++) {
        #pragma unroll
        for (int p = 0; p < 4; p++) {
            int lin = p * 256 + tid;
            int row = lin >> 3, cx = lin & 7;
            const void* src = g_W16 + (size_t)limb * OUT_F * IN_F +
                              (size_t)(n0 + row) * IN_F + it * HKC + cx * 8;
            cp_async16(stg + 2 * H_A + limb * H_A + swz((uint32_t)row, (uint32_t)(cx * 16)), src);
        }
    }
}

__global__ void __launch_bounds__(256, 1) gemm_h_kernel(const float* __restrict__ x) {
    extern __shared__ char sm[];
    uint32_t smb = smem_to_u32(sm);
    int tid = threadIdx.x;
    int l = tid & 31, w = tid >> 5;
    int mw = w & 3, nw = w >> 2;          // 4 x 2 warps, warp tile 32x64
    int n0 = blockIdx.x * 128;
    int j0 = blockIdx.y * 128;
    int jt = blockIdx.y;

    int g = l >> 3, lr = l & 7;
    uint32_t a_row0 = (uint32_t)(mw * 32 + (g & 1) * 8 + lr);
    uint32_t a_kb   = (uint32_t)((g >> 1) * 16);
    uint32_t b_row0 = (uint32_t)(nw * 64 + (g >> 1) * 8 + lr);
    uint32_t b_kb   = (uint32_t)((g & 1) * 16);

    float acc[2][8][4];
    #pragma unroll
    for (int mf = 0; mf < 2; mf++)
        #pragma unroll
        for (int nf = 0; nf < 8; nf++)
            #pragma unroll
            for (int q = 0; q < 4; q++) acc[mf][nf][q] = 0.0f;

    XReg xr;
    h_loadx(xr, x, j0, 0, tid);
    h_stsx(xr, sm, tid);
    h_cpB(smb, n0, 0, tid);
    cp_commit();
    h_loadx(xr, x, j0, 1, tid);

    for (int it = 0; it < 8; ++it) {
        cp_wait<0>();
        __syncthreads();
        if (it + 1 < 8) {
            char* stg = sm + ((it + 1) & 1) * H_STG;
            h_stsx(xr, stg, tid);
            h_cpB(smb + ((it + 1) & 1) * H_STG, n0, it + 1, tid);
            cp_commit();
            if (it + 2 < 8) h_loadx(xr, x, j0, it + 2, tid);
        }
        uint32_t Sb = smb + (it & 1) * H_STG;
        #pragma unroll
        for (int ks = 0; ks < 4; ks++) {
            uint32_t afh[2][4], afl[2][4];
            #pragma unroll
            for (int mf = 0; mf < 2; mf++) {
                uint32_t o = swz(a_row0 + mf * 16u, (uint32_t)(ks * 32) + a_kb);
                ldsm_x4(Sb + o, afh[mf][0], afh[mf][1], afh[mf][2], afh[mf][3]);
                ldsm_x4(Sb + H_A + o, afl[mf][0], afl[mf][1], afl[mf][2], afl[mf][3]);
            }
            #pragma unroll
            for (int nf2 = 0; nf2 < 4; nf2++) {
                uint32_t o = swz(b_row0 + nf2 * 16u, (uint32_t)(ks * 32) + b_kb);
                uint32_t h0, h1, h2, h3, l0, l1, l2, l3;
                ldsm_x4(Sb + 2 * H_A + o, h0, h1, h2, h3);
                ldsm_x4(Sb + 3 * H_A + o, l0, l1, l2, l3);
                #pragma unroll
                for (int mf = 0; mf < 2; mf++) {
                    mma_f16(acc[mf][nf2 * 2 + 0], afh[mf], h0, h1);
                    mma_f16(acc[mf][nf2 * 2 + 1], afh[mf], h2, h3);
                    mma_f16(acc[mf][nf2 * 2 + 0], afl[mf], h0, h1);
                    mma_f16(acc[mf][nf2 * 2 + 1], afl[mf], h2, h3);
                    mma_f16(acc[mf][nf2 * 2 + 0], afh[mf], l0, l1);
                    mma_f16(acc[mf][nf2 * 2 + 1], afh[mf], l2, l3);
                }
            }
        }
    }

    // epilogue: stage h (fp16) into smem [j][k], pitch 130 halves
    __syncthreads();
    unsigned short* hbuf = (unsigned short*)sm;
    const int P = 130;
    #pragma unroll
    for (int mf = 0; mf < 2; mf++) {
        int r = mw * 32 + mf * 16 + (l >> 2);
        #pragma unroll
        for (int nf = 0; nf < 8; nf++) {
            int c = nw * 64 + nf * 8 + (l & 3) * 2;
            *(uint32_t*)&hbuf[r * P + c] = packh(acc[mf][nf][0], acc[mf][nf][1]);
            *(uint32_t*)&hbuf[(r + 8) * P + c] = packh(acc[mf][nf][2], acc[mf][nf][3]);
        }
    }
    __syncthreads();

    // colsum partials
    if (tid < 128) {
        float s = 0.0f;
        #pragma unroll 8
        for (int j = 0; j < 128; j++)
            s += __half2float(__ushort_as_half(hbuf[j * P + tid]));
        g_Sp[jt * OUT_F + n0 + tid] = s;
    }

    // transposed write: g_Bh[n0+kl][j0 .. j0+127]
    {
        int kl = tid >> 1, jh = (tid & 1) * 64;
        unsigned short* dst = g_Bh + (size_t)(n0 + kl) * NROWS + j0 + jh;
        #pragma unroll
        for (int q = 0; q < 8; q++) {
            uint32_t u[4];
            #pragma unroll
            for (int e = 0; e < 4; e++) {
                unsigned short v0 = hbuf[(jh + q * 8 + e * 2 + 0) * P + kl];
                unsigned short v1 = hbuf[(jh + q * 8 + e * 2 + 1) * P + kl];
                u[e] = (uint32_t)v0 | ((uint32_t)v1 << 16);
            }
            *(uint4*)(dst + q * 8) = make_uint4(u[0], u[1], u[2], u[3]);
        }
    }
}

// ---------------------------------------------------------------------------
// Kernel C: reduce colsum partials
// ---------------------------------------------------------------------------
__global__ void reduce_S_kernel() {
    int c = threadIdx.x;
    float s = 0.0f;
    #pragma unroll 8
    for (int jt = 0; jt < 64; jt++) s += g_Sp[jt * OUT_F + c];
    g_S[c] = s;
}

// ---------------------------------------------------------------------------
// Kernel D: masked GEMM (adj>0) @ h, split-K(2), fp16 mma.sync.
// CTA: 64 rows x 256 cols x K=4096 (64 chunks of 64). Grid (2 kt, 128 mt).
// A: register-staged in TWO HALF-LOADS (4 int4 live = 16 regs), STS placed
// between ks blocks so LDG latency hides under mma. A 2 stages (16KB),
// B 2 stages via cp.async (64KB). 80KB -> 2 CTAs/SM. Warp tile 32x64.
// ---------------------------------------------------------------------------
#define KC      64
#define AF_ST   (64 * KC * 2)             // 8 KB fp16
#define B_ST    (256 * KC * 2)            // 32 KB
#define B_BASE  (2 * AF_ST)               // 16 KB
#define GAT_SMEM (B_BASE + 2 * B_ST)      // 80 KB

struct AHalf { int4 v[2]; };   // 32 rows x 64 cols int32 / 256 thr = 2 int4

__device__ __forceinline__ void g_ldgA_half(AHalf& ar, const int* __restrict__ adj,
                                            int m0, int k0, int it, int half, int tid) {
    size_t kk = (size_t)k0 + it * KC;
    #pragma unroll
    for (int p = 0; p < 2; p++) {
        int lin = p * 256 + tid;
        int row = half * 32 + (lin >> 4), c4 = lin & 15;
        ar.v[p] = *(const int4*)(adj + (size_t)(m0 + row) * NROWS + kk + c4 * 4);
    }
}
__device__ __forceinline__ void g_stsA_half(const AHalf& ar, char* base, int half, int tid) {
    #pragma unroll
    for (int p = 0; p < 2; p++) {
        int lin = p * 256 + tid;
        int row = half * 32 + (lin >> 4), c4 = lin & 15;
        int4 a = ar.v[p];
        uint32_t p0 = (a.x ? 0x3C00u : 0u) | (a.y ? 0x3C000000u : 0u);
        uint32_t p1 = (a.z ? 0x3C00u : 0u) | (a.w ? 0x3C000000u : 0u);
        *(uint2*)(base + swz((uint32_t)row, (uint32_t)(c4 * 8))) = make_uint2(p0, p1);
    }
}
__device__ __forceinline__ void g_cpB(uint32_t smaddr, int k0, int it, int tid) {
    size_t kk = (size_t)k0 + it * KC;
    #pragma unroll
    for (int p = 0; p < 8; p++) {
        int lin = p * 256 + tid;
        int row = lin >> 3, cx = lin & 7;
        const void* src = g_Bh + (size_t)row * NROWS + kk + cx * 8;
        cp_async16(smaddr + swz((uint32_t)row, (uint32_t)(cx * 16)), src);
    }
}

__global__ void __launch_bounds__(256, 2) gat_gemm_kernel(const int* __restrict__ adj) {
    extern __shared__ char sm[];
    uint32_t smb = smem_to_u32(sm);
    int tid = threadIdx.x;
    int l = tid & 31, w = tid >> 5;
    int mw = w & 1, nw = w >> 1;          // 2 x 4 warps, warp tile 32x64
    int kt = blockIdx.x;                  // split-K half
    int m0 = blockIdx.y * 64;
    int k0 = kt * (NROWS / 2);

    int g = l >> 3, lr = l & 7;
    uint32_t a_row0 = (uint32_t)(mw * 32 + (g & 1) * 8 + lr);
    uint32_t a_kb   = (uint32_t)((g >> 1) * 16);
    uint32_t b_row0 = (uint32_t)(nw * 64 + (g >> 1) * 8 + lr);
    uint32_t b_kb   = (uint32_t)((g & 1) * 16);

    float acc[2][8][4];
    #pragma unroll
    for (int mf = 0; mf < 2; mf++)
        #pragma unroll
        for (int nf = 0; nf < 8; nf++)
            #pragma unroll
            for (int q = 0; q < 4; q++) acc[mf][nf][q] = 0.0f;

    AHalf ar;
    // prologue: stage 0 fully populated; B(0) in flight
    g_cpB(smb + B_BASE, k0, 0, tid);
    cp_commit();
    g_ldgA_half(ar, adj, m0, k0, 0, 0, tid);
    g_stsA_half(ar, sm, 0, tid);
    g_ldgA_half(ar, adj, m0, k0, 0, 1, tid);
    g_stsA_half(ar, sm, 1, tid);

    const int NCHUNK = (NROWS / 2) / KC;           // 64
    for (int it = 0; it < NCHUNK; ++it) {
        cp_wait<0>();                              // B(it) done
        __syncthreads();                           // A stage (it&1) visible

        char* Anext = sm + ((it + 1) & 1) * AF_ST;
        if (it + 1 < NCHUNK) {
            g_cpB(smb + B_BASE + ((it + 1) & 1) * B_ST, k0, it + 1, tid);
            cp_commit();
            g_ldgA_half(ar, adj, m0, k0, it + 1, 0, tid);
        }

        uint32_t Ab = smb + (it & 1) * AF_ST;
        uint32_t Bb = smb + B_BASE + (it & 1) * B_ST;

        #pragma unroll
        for (int ks = 0; ks < 4; ks++) {
            // interleave A staging between ks blocks (hide LDG latency)
            if (ks == 2 && it + 1 < NCHUNK) {
                g_stsA_half(ar, Anext, 0, tid);
                g_ldgA_half(ar, adj, m0, k0, it + 1, 1, tid);
            }
            uint32_t af[2][4];
            #pragma unroll
            for (int mf = 0; mf < 2; mf++) {
                uint32_t o = swz(a_row0 + mf * 16u, (uint32_t)(ks * 32) + a_kb);
                ldsm_x4(Ab + o, af[mf][0], af[mf][1], af[mf][2], af[mf][3]);
            }
            #pragma unroll
            for (int nf2 = 0; nf2 < 4; nf2++) {
                uint32_t r0, r1, r2, r3;
                uint32_t o = swz(b_row0 + nf2 * 16u, (uint32_t)(ks * 32) + b_kb);
                ldsm_x4(Bb + o, r0, r1, r2, r3);
                #pragma unroll
                for (int mf = 0; mf < 2; mf++) {
                    mma_f16(acc[mf][nf2 * 2 + 0], af[mf], r0, r1);
                    mma_f16(acc[mf][nf2 * 2 + 1], af[mf], r2, r3);
                }
            }
        }
        if (it + 1 < NCHUNK) g_stsA_half(ar, Anext, 1, tid);
    }

    // write split-K partials
    float* P = g_P + (size_t)kt * NROWS * OUT_F;
    #pragma unroll
    for (int mf = 0; mf < 2; mf++) {
        int r0 = m0 + mw * 32 + mf * 16 + (l >> 2);
        #pragma unroll
        for (int nf = 0; nf < 8; nf++) {
            int col = nw * 64 + nf * 8 + (l & 3) * 2;
            *(float2*)(P + (size_t)r0 * OUT_F + col) =
                make_float2(acc[mf][nf][0], acc[mf][nf][1]);
            *(float2*)(P + (size_t)(r0 + 8) * OUT_F + col) =
                make_float2(acc[mf][nf][2], acc[mf][nf][3]);
        }
    }
}

// ---------------------------------------------------------------------------
// Kernel E: combine split-K partials + epilogue
// ---------------------------------------------------------------------------
__global__ void __launch_bounds__(256) combine_kernel(float* __restrict__ out) {
    size_t idx = (size_t)blockIdx.x * 256 + threadIdx.x;
    int c = (int)(idx & (OUT_F - 1));
    float p = g_P[idx] + g_P[(size_t)NROWS * OUT_F + idx];
    out[idx] = NEGC * (g_S[c] - p);
}

// ---------------------------------------------------------------------------
// Launch
// ---------------------------------------------------------------------------
extern "C" void kernel_launch(void* const* d_in, const int* in_sizes, int n_in,
                              void* d_out, int out_size) {
    const float* x   = (const float*)d_in[0];   // [8192, 512]
    const float* W   = (const float*)d_in[1];   // [512, 256]
    const int*   adj = (const int*)d_in[3];     // [8192, 8192]
    float* out = (float*)d_out;                 // [8192, 256]

    convert_W_kernel<<<512, 256>>>(W);

    cudaFuncSetAttribute(gemm_h_kernel, cudaFuncAttributeMaxDynamicSharedMemorySize, H_SMEM);
    gemm_h_kernel<<<dim3(2, 64), 256, H_SMEM>>>(x);

    reduce_S_kernel<<<1, 256>>>();

    cudaFuncSetAttribute(gat_gemm_kernel, cudaFuncAttributeMaxDynamicSharedMemorySize, GAT_SMEM);
    gat_gemm_kernel<<<dim3(2, NROWS / 64), 256, GAT_SMEM>>>(adj);

    combine_kernel<<<(NROWS * OUT_F) / 256, 256>>>(out);
}

// round 13
// speedup vs baseline: 1.0869x; 1.0869x over previous
#include <cuda_runtime.h>
#include <cuda_fp16.h>
#include <cstdint>

// ---------------------------------------------------------------------------
// GAT layer. N=8192, IN_F=512, OUT_F=256.
// out = NEG * (colsum(h) - (adj>0) @ h),  h = x @ W, NEG = -9e15.
// R13: GAT kernel reverted to EXACT R7 mainloop (measured 129.5us). Split-K
// combine replaced by atomicAdd epilogue into prefilled out (saves ~10us and
// one launch). 5 launches: convert_W, gemm_h, reduce_S, prefill, gat.
// ---------------------------------------------------------------------------

#define NROWS   8192
#define IN_F    512
#define OUT_F   256
#define NEGC    (-9.0e15f)

// Static scratch
__device__ unsigned short g_Bh[(size_t)OUT_F * NROWS];   // h^T fp16 [k][j]
__device__ unsigned short g_W16[2 * OUT_F * IN_F];       // W^T fp16 limbs [limb][n][k]
__device__ float          g_Sp[64 * OUT_F];              // per-j-tile colsum partials
__device__ float          g_S[OUT_F];                    // colsum(h)

// ---------------------------------------------------------------------------
// helpers
// ---------------------------------------------------------------------------
__device__ __forceinline__ uint32_t smem_to_u32(const void* p) {
    uint32_t a;
    asm("{ .reg .u64 t; cvta.to.shared.u64 t, %1; cvt.u32.u64 %0, t; }" : "=r"(a) : "l"(p));
    return a;
}
__device__ __forceinline__ void cp_async16(uint32_t dst, const void* src) {
    asm volatile("cp.async.cg.shared.global [%0], [%1], 16;" :: "r"(dst), "l"(src));
}
__device__ __forceinline__ void cp_commit() { asm volatile("cp.async.commit_group;"); }
template <int N>
__device__ __forceinline__ void cp_wait() { asm volatile("cp.async.wait_group %0;" :: "n"(N)); }

__device__ __forceinline__ void ldsm_x4(uint32_t addr, uint32_t& r0, uint32_t& r1,
                                        uint32_t& r2, uint32_t& r3) {
    asm volatile("ldmatrix.sync.aligned.m8n8.x4.shared.b16 {%0,%1,%2,%3}, [%4];"
                 : "=r"(r0), "=r"(r1), "=r"(r2), "=r"(r3) : "r"(addr));
}
__device__ __forceinline__ void mma_f16(float* c, const uint32_t* a, uint32_t b0, uint32_t b1) {
    asm volatile("mma.sync.aligned.m16n8k16.row.col.f32.f16.f16.f32 "
                 "{%0,%1,%2,%3}, {%4,%5,%6,%7}, {%8,%9}, {%0,%1,%2,%3};"
                 : "+f"(c[0]), "+f"(c[1]), "+f"(c[2]), "+f"(c[3])
                 : "r"(a[0]), "r"(a[1]), "r"(a[2]), "r"(a[3]), "r"(b0), "r"(b1));
}
__device__ __forceinline__ uint32_t swz(uint32_t row, uint32_t col) {
    return row * 128u + (col ^ ((row & 7u) * 16u));
}
__device__ __forceinline__ uint32_t packh(float a, float b) {
    return (uint32_t)__half_as_ushort(__float2half_rn(a)) |
           ((uint32_t)__half_as_ushort(__float2half_rn(b)) << 16);
}

// ---------------------------------------------------------------------------
// Kernel A: split W into fp16 hi/lo limbs, transposed: g_W16[limb][n][k]
// ---------------------------------------------------------------------------
__global__ void __launch_bounds__(256) convert_W_kernel(const float* __restrict__ W) {
    int idx = blockIdx.x * 256 + threadIdx.x;       // 131072 total
    int n = idx & 255, k = idx >> 8;
    float v = W[(size_t)k * OUT_F + n];
    __half hi = __float2half_rn(v);
    __half lo = __float2half_rn(v - __half2float(hi));
    g_W16[n * IN_F + k] = __half_as_ushort(hi);
    g_W16[OUT_F * IN_F + n * IN_F + k] = __half_as_ushort(lo);
}

// ---------------------------------------------------------------------------
// Kernel B: h = x @ W on tensor cores, fp16 2-limb x 2-limb (3 terms).
// CTA: 128 j-rows x 128 n-cols, K=512 (8 chunks of 64). Grid (2 nt, 64 jt).
// Emits g_Bh[k][j] fp16 and g_Sp[jt][k] colsum partials.
// ---------------------------------------------------------------------------
#define HKC   64
#define H_A   (128 * HKC * 2)   // 16 KB per limb tile
#define H_STG (4 * H_A)         // Ahi|Alo|Bhi|Blo = 64 KB
#define H_SMEM (2 * H_STG)      // 128 KB

struct XReg { float4 v[8]; };

__device__ __forceinline__ void h_loadx(XReg& xr, const float* __restrict__ x,
                                        int j0, int it, int tid) {
    #pragma unroll
    for (int p = 0; p < 8; p++) {
        int lin = p * 256 + tid;
        int row = lin >> 4, c4 = lin & 15;
        xr.v[p] = *(const float4*)(x + (size_t)(j0 + row) * IN_F + it * HKC + c4 * 4);
    }
}
__device__ __forceinline__ void h_stsx(const XReg& xr, char* stg, int tid) {
    #pragma unroll
    for (int p = 0; p < 8; p++) {
        int lin = p * 256 + tid;
        int row = lin >> 4, c4 = lin & 15;
        float4 v = xr.v[p];
        __half hx = __float2half_rn(v.x), hy = __float2half_rn(v.y);
        __half hz = __float2half_rn(v.z), hw = __float2half_rn(v.w);
        uint32_t o = swz((uint32_t)row, (uint32_t)(c4 * 8));
        *(uint2*)(stg + o) = make_uint2(
            (uint32_t)__half_as_ushort(hx) | ((uint32_t)__half_as_ushort(hy) << 16),
            (uint32_t)__half_as_ushort(hz) | ((uint32_t)__half_as_ushort(hw) << 16));
        *(uint2*)(stg + H_A + o) = make_uint2(
            packh(v.x - __half2float(hx), v.y - __half2float(hy)),
            packh(v.z - __half2float(hz), v.w - __half2float(hw)));
    }
}
__device__ __forceinline__ void h_cpB(uint32_t stg, int n0, int it, int tid) {
    #pragma unroll
    for (int limb = 0; limb < 2; limb++) {
        #pragma unroll
        for (int p = 0; p < 4; p++) {
            int lin = p * 256 + tid;
            int row = lin >> 3, cx = lin & 7;
            const void* src = g_W16 + (size_t)limb * OUT_F * IN_F +
                              (size_t)(n0 + row) * IN_F + it * HKC + cx * 8;
            cp_async16(stg + 2 * H_A + limb * H_A + swz((uint32_t)row, (uint32_t)(cx * 16)), src);
        }
    }
}

__global__ void __launch_bounds__(256, 1) gemm_h_kernel(const float* __restrict__ x) {
    extern __shared__ char sm[];
    uint32_t smb = smem_to_u32(sm);
    int tid = threadIdx.x;
    int l = tid & 31, w = tid >> 5;
    int mw = w & 3, nw = w >> 2;          // 4 x 2 warps, warp tile 32x64
    int n0 = blockIdx.x * 128;
    int j0 = blockIdx.y * 128;
    int jt = blockIdx.y;

    int g = l >> 3, lr = l & 7;
    uint32_t a_row0 = (uint32_t)(mw * 32 + (g & 1) * 8 + lr);
    uint32_t a_kb   = (uint32_t)((g >> 1) * 16);
    uint32_t b_row0 = (uint32_t)(nw * 64 + (g >> 1) * 8 + lr);
    uint32_t b_kb   = (uint32_t)((g & 1) * 16);

    float acc[2][8][4];
    #pragma unroll
    for (int mf = 0; mf < 2; mf++)
        #pragma unroll
        for (int nf = 0; nf < 8; nf++)
            #pragma unroll
            for (int q = 0; q < 4; q++) acc[mf][nf][q] = 0.0f;

    XReg xr;
    h_loadx(xr, x, j0, 0, tid);
    h_stsx(xr, sm, tid);
    h_cpB(smb, n0, 0, tid);
    cp_commit();
    h_loadx(xr, x, j0, 1, tid);

    for (int it = 0; it < 8; ++it) {
        cp_wait<0>();
        __syncthreads();
        if (it + 1 < 8) {
            char* stg = sm + ((it + 1) & 1) * H_STG;
            h_stsx(xr, stg, tid);
            h_cpB(smb + ((it + 1) & 1) * H_STG, n0, it + 1, tid);
            cp_commit();
            if (it + 2 < 8) h_loadx(xr, x, j0, it + 2, tid);
        }
        uint32_t Sb = smb + (it & 1) * H_STG;
        #pragma unroll
        for (int ks = 0; ks < 4; ks++) {
            uint32_t afh[2][4], afl[2][4];
            #pragma unroll
            for (int mf = 0; mf < 2; mf++) {
                uint32_t o = swz(a_row0 + mf * 16u, (uint32_t)(ks * 32) + a_kb);
                ldsm_x4(Sb + o, afh[mf][0], afh[mf][1], afh[mf][2], afh[mf][3]);
                ldsm_x4(Sb + H_A + o, afl[mf][0], afl[mf][1], afl[mf][2], afl[mf][3]);
            }
            #pragma unroll
            for (int nf2 = 0; nf2 < 4; nf2++) {
                uint32_t o = swz(b_row0 + nf2 * 16u, (uint32_t)(ks * 32) + b_kb);
                uint32_t h0, h1, h2, h3, l0, l1, l2, l3;
                ldsm_x4(Sb + 2 * H_A + o, h0, h1, h2, h3);
                ldsm_x4(Sb + 3 * H_A + o, l0, l1, l2, l3);
                #pragma unroll
                for (int mf = 0; mf < 2; mf++) {
                    mma_f16(acc[mf][nf2 * 2 + 0], afh[mf], h0, h1);
                    mma_f16(acc[mf][nf2 * 2 + 1], afh[mf], h2, h3);
                    mma_f16(acc[mf][nf2 * 2 + 0], afl[mf], h0, h1);
                    mma_f16(acc[mf][nf2 * 2 + 1], afl[mf], h2, h3);
                    mma_f16(acc[mf][nf2 * 2 + 0], afh[mf], l0, l1);
                    mma_f16(acc[mf][nf2 * 2 + 1], afh[mf], l2, l3);
                }
            }
        }
    }

    // epilogue: stage h (fp16) into smem [j][k], pitch 130 halves
    __syncthreads();
    unsigned short* hbuf = (unsigned short*)sm;
    const int P = 130;
    #pragma unroll
    for (int mf = 0; mf < 2; mf++) {
        int r = mw * 32 + mf * 16 + (l >> 2);
        #pragma unroll
        for (int nf = 0; nf < 8; nf++) {
            int c = nw * 64 + nf * 8 + (l & 3) * 2;
            *(uint32_t*)&hbuf[r * P + c] = packh(acc[mf][nf][0], acc[mf][nf][1]);
            *(uint32_t*)&hbuf[(r + 8) * P + c] = packh(acc[mf][nf][2], acc[mf][nf][3]);
        }
    }
    __syncthreads();

    // colsum partials
    if (tid < 128) {
        float s = 0.0f;
        #pragma unroll 8
        for (int j = 0; j < 128; j++)
            s += __half2float(__ushort_as_half(hbuf[j * P + tid]));
        g_Sp[jt * OUT_F + n0 + tid] = s;
    }

    // transposed write: g_Bh[n0+kl][j0 .. j0+127]
    {
        int kl = tid >> 1, jh = (tid & 1) * 64;
        unsigned short* dst = g_Bh + (size_t)(n0 + kl) * NROWS + j0 + jh;
        #pragma unroll
        for (int q = 0; q < 8; q++) {
            uint32_t u[4];
            #pragma unroll
            for (int e = 0; e < 4; e++) {
                unsigned short v0 = hbuf[(jh + q * 8 + e * 2 + 0) * P + kl];
                unsigned short v1 = hbuf[(jh + q * 8 + e * 2 + 1) * P + kl];
                u[e] = (uint32_t)v0 | ((uint32_t)v1 << 16);
            }
            *(uint4*)(dst + q * 8) = make_uint4(u[0], u[1], u[2], u[3]);
        }
    }
}

// ---------------------------------------------------------------------------
// Kernel C: reduce colsum partials
// ---------------------------------------------------------------------------
__global__ void reduce_S_kernel() {
    int c = threadIdx.x;
    float s = 0.0f;
    #pragma unroll 8
    for (int jt = 0; jt < 64; jt++) s += g_Sp[jt * OUT_F + c];
    g_S[c] = s;
}

// ---------------------------------------------------------------------------
// Kernel C2: prefill out = NEG * S[c]  (GAT CTAs atomically add 9e15*p)
// ---------------------------------------------------------------------------
__global__ void __launch_bounds__(256) prefill_out_kernel(float* __restrict__ out) {
    int idx = blockIdx.x * 256 + threadIdx.x;      // float4 index, 524288 total
    int c4 = (idx * 4) & (OUT_F - 1);
    float4 v = make_float4(NEGC * g_S[c4], NEGC * g_S[c4 + 1],
                           NEGC * g_S[c4 + 2], NEGC * g_S[c4 + 3]);
    ((float4*)out)[idx] = v;
}

// ---------------------------------------------------------------------------
// Kernel D: masked GEMM (adj>0) @ h, split-K(2), fp16 mma.sync.
// EXACT R7 mainloop (measured 129.5us): CTA 64x256 x K=4096, grid (2,128).
// A ring 3 stages (8KB, register-staged 3 chunks ahead), B ring 2 stages
// (32KB cp.async) -> 88KB, 2 CTAs/SM. Warp tile 32x64.
// Epilogue: atomicAdd(out, 9e15 * partial)  [out prefilled with NEG*S].
// ---------------------------------------------------------------------------
#define KC     64
#define A_ST   (64 * KC * 2)              // 8 KB
#define B_ST   (256 * KC * 2)             // 32 KB
#define B_BASE (3 * A_ST)                 // 24 KB
#define GAT_SMEM (B_BASE + 2 * B_ST)      // 88 KB

struct AReg { int4 v[4]; };

__device__ __forceinline__ void g_ldgA(AReg& ar, const int* __restrict__ adj,
                                       int m0, int k0, int it, int tid) {
    size_t kk = (size_t)k0 + it * KC;
    #pragma unroll
    for (int p = 0; p < 4; p++) {
        int lin = p * 256 + tid;
        int row = lin >> 4, c4 = lin & 15;
        ar.v[p] = *(const int4*)(adj + (size_t)(m0 + row) * NROWS + kk + c4 * 4);
    }
}
__device__ __forceinline__ void g_stsA(const AReg& ar, char* base, int tid) {
    #pragma unroll
    for (int p = 0; p < 4; p++) {
        int lin = p * 256 + tid;
        int row = lin >> 4, c4 = lin & 15;
        int4 a = ar.v[p];
        uint32_t p0 = (a.x ? 0x3C00u : 0u) | (a.y ? 0x3C000000u : 0u);
        uint32_t p1 = (a.z ? 0x3C00u : 0u) | (a.w ? 0x3C000000u : 0u);
        *(uint2*)(base + swz((uint32_t)row, (uint32_t)(c4 * 8))) = make_uint2(p0, p1);
    }
}
__device__ __forceinline__ void g_cpB(uint32_t smaddr, int k0, int it, int tid) {
    size_t kk = (size_t)k0 + it * KC;
    #pragma unroll
    for (int p = 0; p < 8; p++) {
        int lin = p * 256 + tid;
        int row = lin >> 3, cx = lin & 7;
        const void* src = g_Bh + (size_t)row * NROWS + kk + cx * 8;
        cp_async16(smaddr + swz((uint32_t)row, (uint32_t)(cx * 16)), src);
    }
}

__global__ void __launch_bounds__(256, 2) gat_gemm_kernel(const int* __restrict__ adj,
                                                          float* __restrict__ out) {
    extern __shared__ char sm[];
    uint32_t smb = smem_to_u32(sm);
    int tid = threadIdx.x;
    int l = tid & 31, w = tid >> 5;
    int mw = w & 1, nw = w >> 1;          // 2 x 4 warps, warp tile 32x64
    int kt = blockIdx.x;                  // split-K half
    int m0 = blockIdx.y * 64;
    int k0 = kt * (NROWS / 2);

    int g = l >> 3, lr = l & 7;
    uint32_t a_row0 = (uint32_t)(mw * 32 + (g & 1) * 8 + lr);
    uint32_t a_kb   = (uint32_t)((g >> 1) * 16);
    uint32_t b_row0 = (uint32_t)(nw * 64 + (g >> 1) * 8 + lr);
    uint32_t b_kb   = (uint32_t)((g & 1) * 16);

    float acc[2][8][4];
    #pragma unroll
    for (int mf = 0; mf < 2; mf++)
        #pragma unroll
        for (int nf = 0; nf < 8; nf++)
            #pragma unroll
            for (int q = 0; q < 4; q++) acc[mf][nf][q] = 0.0f;

    AReg ar;
    g_ldgA(ar, adj, m0, k0, 0, tid); g_stsA(ar, sm + 0 * A_ST, tid);
    g_ldgA(ar, adj, m0, k0, 1, tid); g_stsA(ar, sm + 1 * A_ST, tid);
    g_ldgA(ar, adj, m0, k0, 2, tid);
    g_cpB(smb + B_BASE, k0, 0, tid);
    cp_commit();

    const int NCHUNK = (NROWS / 2) / KC;  // 64
    for (int it = 0; it < NCHUNK; ++it) {
        cp_wait<0>();
        __syncthreads();
        if (it + 1 < NCHUNK) {
            g_cpB(smb + B_BASE + ((it + 1) & 1) * B_ST, k0, it + 1, tid);
            cp_commit();
        }
        if (it + 2 < NCHUNK) {
            g_stsA(ar, sm + ((it + 2) % 3) * A_ST, tid);
            if (it + 3 < NCHUNK) g_ldgA(ar, adj, m0, k0, it + 3, tid);
        }

        uint32_t Ab = smb + (it % 3) * A_ST;
        uint32_t Bb = smb + B_BASE + (it & 1) * B_ST;
        #pragma unroll
        for (int ks = 0; ks < 4; ks++) {
            uint32_t af[2][4];
            #pragma unroll
            for (int mf = 0; mf < 2; mf++) {
                uint32_t o = swz(a_row0 + mf * 16u, (uint32_t)(ks * 32) + a_kb);
                ldsm_x4(Ab + o, af[mf][0], af[mf][1], af[mf][2], af[mf][3]);
            }
            #pragma unroll
            for (int nf2 = 0; nf2 < 4; nf2++) {
                uint32_t r0, r1, r2, r3;
                uint32_t o = swz(b_row0 + nf2 * 16u, (uint32_t)(ks * 32) + b_kb);
                ldsm_x4(Bb + o, r0, r1, r2, r3);
                #pragma unroll
                for (int mf = 0; mf < 2; mf++) {
                    mma_f16(acc[mf][nf2 * 2 + 0], af[mf], r0, r1);
                    mma_f16(acc[mf][nf2 * 2 + 1], af[mf], r2, r3);
                }
            }
        }
    }

    // epilogue: out += 9e15 * partial  (out prefilled with NEG*S)
    #pragma unroll
    for (int mf = 0; mf < 2; mf++) {
        int r0 = m0 + mw * 32 + mf * 16 + (l >> 2);
        #pragma unroll
        for (int nf = 0; nf < 8; nf++) {
            int col = nw * 64 + nf * 8 + (l & 3) * 2;
            atomicAdd(out + (size_t)r0 * OUT_F + col,       -NEGC * acc[mf][nf][0]);
            atomicAdd(out + (size_t)r0 * OUT_F + col + 1,   -NEGC * acc[mf][nf][1]);
            atomicAdd(out + (size_t)(r0 + 8) * OUT_F + col,     -NEGC * acc[mf][nf][2]);
            atomicAdd(out + (size_t)(r0 + 8) * OUT_F + col + 1, -NEGC * acc[mf][nf][3]);
        }
    }
}

// ---------------------------------------------------------------------------
// Launch
// ---------------------------------------------------------------------------
extern "C" void kernel_launch(void* const* d_in, const int* in_sizes, int n_in,
                              void* d_out, int out_size) {
    const float* x   = (const float*)d_in[0];   // [8192, 512]
    const float* W   = (const float*)d_in[1];   // [512, 256]
    const int*   adj = (const int*)d_in[3];     // [8192, 8192]
    float* out = (float*)d_out;                 // [8192, 256]

    convert_W_kernel<<<512, 256>>>(W);

    cudaFuncSetAttribute(gemm_h_kernel, cudaFuncAttributeMaxDynamicSharedMemorySize, H_SMEM);
    gemm_h_kernel<<<dim3(2, 64), 256, H_SMEM>>>(x);

    reduce_S_kernel<<<1, 256>>>();

    prefill_out_kernel<<<(NROWS * OUT_F / 4) / 256, 256>>>(out);

    cudaFuncSetAttribute(gat_gemm_kernel, cudaFuncAttributeMaxDynamicSharedMemorySize, GAT_SMEM);
    gat_gemm_kernel<<<dim3(2, NROWS / 64), 256, GAT_SMEM>>>(adj, out);
}

// round 14
// speedup vs baseline: 1.1810x; 1.0866x over previous
#include <cuda_runtime.h>
#include <cuda_fp16.h>
#include <cstdint>

// ---------------------------------------------------------------------------
// GAT layer. N=8192, IN_F=512, OUT_F=256.
// out = NEG * (colsum(h) - (adj>0) @ h),  h = x @ W, NEG = -9e15.
// R14: GAT kernel = frozen R7 mainloop, but statically load-balanced over
// grid=296 (=148 SMs x occ2): 2048 work units (128 mt x 16 kt, K=512 each),
// CTA c owns a contiguous range (<=2 mt segments). reduce_S+prefill fused.
// 4 launches: convert_W, gemm_h, prefill_out, gat.
// ---------------------------------------------------------------------------

#define NROWS   8192
#define IN_F    512
#define OUT_F   256
#define NEGC    (-9.0e15f)

// Static scratch
__device__ unsigned short g_Bh[(size_t)OUT_F * NROWS];   // h^T fp16 [k][j]
__device__ unsigned short g_W16[2 * OUT_F * IN_F];       // W^T fp16 limbs [limb][n][k]
__device__ float          g_Sp[64 * OUT_F];              // per-j-tile colsum partials

// ---------------------------------------------------------------------------
// helpers
// ---------------------------------------------------------------------------
__device__ __forceinline__ uint32_t smem_to_u32(const void* p) {
    uint32_t a;
    asm("{ .reg .u64 t; cvta.to.shared.u64 t, %1; cvt.u32.u64 %0, t; }" : "=r"(a) : "l"(p));
    return a;
}
__device__ __forceinline__ void cp_async16(uint32_t dst, const void* src) {
    asm volatile("cp.async.cg.shared.global [%0], [%1], 16;" :: "r"(dst), "l"(src));
}
__device__ __forceinline__ void cp_commit() { asm volatile("cp.async.commit_group;"); }
template <int N>
__device__ __forceinline__ void cp_wait() { asm volatile("cp.async.wait_group %0;" :: "n"(N)); }

__device__ __forceinline__ void ldsm_x4(uint32_t addr, uint32_t& r0, uint32_t& r1,
                                        uint32_t& r2, uint32_t& r3) {
    asm volatile("ldmatrix.sync.aligned.m8n8.x4.shared.b16 {%0,%1,%2,%3}, [%4];"
                 : "=r"(r0), "=r"(r1), "=r"(r2), "=r"(r3) : "r"(addr));
}
__device__ __forceinline__ void mma_f16(float* c, const uint32_t* a, uint32_t b0, uint32_t b1) {
    asm volatile("mma.sync.aligned.m16n8k16.row.col.f32.f16.f16.f32 "
                 "{%0,%1,%2,%3}, {%4,%5,%6,%7}, {%8,%9}, {%0,%1,%2,%3};"
                 : "+f"(c[0]), "+f"(c[1]), "+f"(c[2]), "+f"(c[3])
                 : "r"(a[0]), "r"(a[1]), "r"(a[2]), "r"(a[3]), "r"(b0), "r"(b1));
}
__device__ __forceinline__ uint32_t swz(uint32_t row, uint32_t col) {
    return row * 128u + (col ^ ((row & 7u) * 16u));
}
__device__ __forceinline__ uint32_t packh(float a, float b) {
    return (uint32_t)__half_as_ushort(__float2half_rn(a)) |
           ((uint32_t)__half_as_ushort(__float2half_rn(b)) << 16);
}

// ---------------------------------------------------------------------------
// Kernel A: split W into fp16 hi/lo limbs, transposed: g_W16[limb][n][k]
// ---------------------------------------------------------------------------
__global__ void __launch_bounds__(256) convert_W_kernel(const float* __restrict__ W) {
    int idx = blockIdx.x * 256 + threadIdx.x;       // 131072 total
    int n = idx & 255, k = idx >> 8;
    float v = W[(size_t)k * OUT_F + n];
    __half hi = __float2half_rn(v);
    __half lo = __float2half_rn(v - __half2float(hi));
    g_W16[n * IN_F + k] = __half_as_ushort(hi);
    g_W16[OUT_F * IN_F + n * IN_F + k] = __half_as_ushort(lo);
}

// ---------------------------------------------------------------------------
// Kernel B: h = x @ W on tensor cores, fp16 2-limb x 2-limb (3 terms).
// CTA: 128 j-rows x 128 n-cols, K=512 (8 chunks of 64). Grid (2 nt, 64 jt).
// Emits g_Bh[k][j] fp16 and g_Sp[jt][k] colsum partials.
// ---------------------------------------------------------------------------
#define HKC   64
#define H_A   (128 * HKC * 2)   // 16 KB per limb tile
#define H_STG (4 * H_A)         // Ahi|Alo|Bhi|Blo = 64 KB
#define H_SMEM (2 * H_STG)      // 128 KB

struct XReg { float4 v[8]; };

__device__ __forceinline__ void h_loadx(XReg& xr, const float* __restrict__ x,
                                        int j0, int it, int tid) {
    #pragma unroll
    for (int p = 0; p < 8; p++) {
        int lin = p * 256 + tid;
        int row = lin >> 4, c4 = lin & 15;
        xr.v[p] = *(const float4*)(x + (size_t)(j0 + row) * IN_F + it * HKC + c4 * 4);
    }
}
__device__ __forceinline__ void h_stsx(const XReg& xr, char* stg, int tid) {
    #pragma unroll
    for (int p = 0; p < 8; p++) {
        int lin = p * 256 + tid;
        int row = lin >> 4, c4 = lin & 15;
        float4 v = xr.v[p];
        __half hx = __float2half_rn(v.x), hy = __float2half_rn(v.y);
        __half hz = __float2half_rn(v.z), hw = __float2half_rn(v.w);
        uint32_t o = swz((uint32_t)row, (uint32_t)(c4 * 8));
        *(uint2*)(stg + o) = make_uint2(
            (uint32_t)__half_as_ushort(hx) | ((uint32_t)__half_as_ushort(hy) << 16),
            (uint32_t)__half_as_ushort(hz) | ((uint32_t)__half_as_ushort(hw) << 16));
        *(uint2*)(stg + H_A + o) = make_uint2(
            packh(v.x - __half2float(hx), v.y - __half2float(hy)),
            packh(v.z - __half2float(hz), v.w - __half2float(hw)));
    }
}
__device__ __forceinline__ void h_cpB(uint32_t stg, int n0, int it, int tid) {
    #pragma unroll
    for (int limb = 0; limb < 2; limb++) {
        #pragma unroll
        for (int p = 0; p < 4; p++) {
            int lin = p * 256 + tid;
            int row = lin >> 3, cx = lin & 7;
            const void* src = g_W16 + (size_t)limb * OUT_F * IN_F +
                              (size_t)(n0 + row) * IN_F + it * HKC + cx * 8;
            cp_async16(stg + 2 * H_A + limb * H_A + swz((uint32_t)row, (uint32_t)(cx * 16)), src);
        }
    }
}

__global__ void __launch_bounds__(256, 1) gemm_h_kernel(const float* __restrict__ x) {
    extern __shared__ char sm[];
    uint32_t smb = smem_to_u32(sm);
    int tid = threadIdx.x;
    int l = tid & 31, w = tid >> 5;
    int mw = w & 3, nw = w >> 2;          // 4 x 2 warps, warp tile 32x64
    int n0 = blockIdx.x * 128;
    int j0 = blockIdx.y * 128;
    int jt = blockIdx.y;

    int g = l >> 3, lr = l & 7;
    uint32_t a_row0 = (uint32_t)(mw * 32 + (g & 1) * 8 + lr);
    uint32_t a_kb   = (uint32_t)((g >> 1) * 16);
    uint32_t b_row0 = (uint32_t)(nw * 64 + (g >> 1) * 8 + lr);
    uint32_t b_kb   = (uint32_t)((g & 1) * 16);

    float acc[2][8][4];
    #pragma unroll
    for (int mf = 0; mf < 2; mf++)
        #pragma unroll
        for (int nf = 0; nf < 8; nf++)
            #pragma unroll
            for (int q = 0; q < 4; q++) acc[mf][nf][q] = 0.0f;

    XReg xr;
    h_loadx(xr, x, j0, 0, tid);
    h_stsx(xr, sm, tid);
    h_cpB(smb, n0, 0, tid);
    cp_commit();
    h_loadx(xr, x, j0, 1, tid);

    for (int it = 0; it < 8; ++it) {
        cp_wait<0>();
        __syncthreads();
        if (it + 1 < 8) {
            char* stg = sm + ((it + 1) & 1) * H_STG;
            h_stsx(xr, stg, tid);
            h_cpB(smb + ((it + 1) & 1) * H_STG, n0, it + 1, tid);
            cp_commit();
            if (it + 2 < 8) h_loadx(xr, x, j0, it + 2, tid);
        }
        uint32_t Sb = smb + (it & 1) * H_STG;
        #pragma unroll
        for (int ks = 0; ks < 4; ks++) {
            uint32_t afh[2][4], afl[2][4];
            #pragma unroll
            for (int mf = 0; mf < 2; mf++) {
                uint32_t o = swz(a_row0 + mf * 16u, (uint32_t)(ks * 32) + a_kb);
                ldsm_x4(Sb + o, afh[mf][0], afh[mf][1], afh[mf][2], afh[mf][3]);
                ldsm_x4(Sb + H_A + o, afl[mf][0], afl[mf][1], afl[mf][2], afl[mf][3]);
            }
            #pragma unroll
            for (int nf2 = 0; nf2 < 4; nf2++) {
                uint32_t o = swz(b_row0 + nf2 * 16u, (uint32_t)(ks * 32) + b_kb);
                uint32_t h0, h1, h2, h3, l0, l1, l2, l3;
                ldsm_x4(Sb + 2 * H_A + o, h0, h1, h2, h3);
                ldsm_x4(Sb + 3 * H_A + o, l0, l1, l2, l3);
                #pragma unroll
                for (int mf = 0; mf < 2; mf++) {
                    mma_f16(acc[mf][nf2 * 2 + 0], afh[mf], h0, h1);
                    mma_f16(acc[mf][nf2 * 2 + 1], afh[mf], h2, h3);
                    mma_f16(acc[mf][nf2 * 2 + 0], afl[mf], h0, h1);
                    mma_f16(acc[mf][nf2 * 2 + 1], afl[mf], h2, h3);
                    mma_f16(acc[mf][nf2 * 2 + 0], afh[mf], l0, l1);
                    mma_f16(acc[mf][nf2 * 2 + 1], afh[mf], l2, l3);
                }
            }
        }
    }

    // epilogue: stage h (fp16) into smem [j][k], pitch 130 halves
    __syncthreads();
    unsigned short* hbuf = (unsigned short*)sm;
    const int P = 130;
    #pragma unroll
    for (int mf = 0; mf < 2; mf++) {
        int r = mw * 32 + mf * 16 + (l >> 2);
        #pragma unroll
        for (int nf = 0; nf < 8; nf++) {
            int c = nw * 64 + nf * 8 + (l & 3) * 2;
            *(uint32_t*)&hbuf[r * P + c] = packh(acc[mf][nf][0], acc[mf][nf][1]);
            *(uint32_t*)&hbuf[(r + 8) * P + c] = packh(acc[mf][nf][2], acc[mf][nf][3]);
        }
    }
    __syncthreads();

    // colsum partials
    if (tid < 128) {
        float s = 0.0f;
        #pragma unroll 8
        for (int j = 0; j < 128; j++)
            s += __half2float(__ushort_as_half(hbuf[j * P + tid]));
        g_Sp[jt * OUT_F + n0 + tid] = s;
    }

    // transposed write: g_Bh[n0+kl][j0 .. j0+127]
    {
        int kl = tid >> 1, jh = (tid & 1) * 64;
        unsigned short* dst = g_Bh + (size_t)(n0 + kl) * NROWS + j0 + jh;
        #pragma unroll
        for (int q = 0; q < 8; q++) {
            uint32_t u[4];
            #pragma unroll
            for (int e = 0; e < 4; e++) {
                unsigned short v0 = hbuf[(jh + q * 8 + e * 2 + 0) * P + kl];
                unsigned short v1 = hbuf[(jh + q * 8 + e * 2 + 1) * P + kl];
                u[e] = (uint32_t)v0 | ((uint32_t)v1 << 16);
            }
            *(uint4*)(dst + q * 8) = make_uint4(u[0], u[1], u[2], u[3]);
        }
    }
}

// ---------------------------------------------------------------------------
// Kernel C: fused colsum-reduce + prefill: out[r][c] = NEG * S[c]
// Grid 128 blocks; block b reduces g_Sp then fills rows [64b, 64b+64).
// ---------------------------------------------------------------------------
__global__ void __launch_bounds__(256) prefill_out_kernel(float* __restrict__ out) {
    __shared__ float sS[256];
    int t = threadIdx.x;
    float s = 0.0f;
    #pragma unroll 8
    for (int jt = 0; jt < 64; jt++) s += g_Sp[jt * OUT_F + t];
    sS[t] = NEGC * s;
    __syncthreads();
    float v = sS[t];
    float* base = out + (size_t)blockIdx.x * 64 * OUT_F + t;
    #pragma unroll 8
    for (int r = 0; r < 64; r++) base[r * OUT_F] = v;
}

// ---------------------------------------------------------------------------
// Kernel D: masked GEMM (adj>0) @ h. Frozen R7 mainloop, statically
// load-balanced: grid 296 (=148 SMs x occ2). 2048 units (mt 128 x kt 16,
// K=512/unit); CTA c owns a contiguous range (272 CTAs x7, 24 x6) spanning
// <=2 mt segments; per segment run the mainloop over its contiguous chunks,
// then flush via atomicAdd into prefilled out.
// A ring 3 stages (8KB, reg-staged 3 ahead), B ring 2 stages (32KB cp.async)
// -> 88KB, 2 CTAs/SM. 8 warps = 2mw x 4nw, warp tile 32x64.
// ---------------------------------------------------------------------------
#define KC     64
#define A_ST   (64 * KC * 2)              // 8 KB
#define B_ST   (256 * KC * 2)             // 32 KB
#define B_BASE (3 * A_ST)                 // 24 KB
#define GAT_SMEM (B_BASE + 2 * B_ST)      // 88 KB

struct AReg { int4 v[4]; };

__device__ __forceinline__ void g_ldgA(AReg& ar, const int* __restrict__ adj,
                                       int m0, int ch, int tid) {
    size_t kk = (size_t)ch * KC;
    #pragma unroll
    for (int p = 0; p < 4; p++) {
        int lin = p * 256 + tid;
        int row = lin >> 4, c4 = lin & 15;
        ar.v[p] = *(const int4*)(adj + (size_t)(m0 + row) * NROWS + kk + c4 * 4);
    }
}
__device__ __forceinline__ void g_stsA(const AReg& ar, char* base, int tid) {
    #pragma unroll
    for (int p = 0; p < 4; p++) {
        int lin = p * 256 + tid;
        int row = lin >> 4, c4 = lin & 15;
        int4 a = ar.v[p];
        uint32_t p0 = (a.x ? 0x3C00u : 0u) | (a.y ? 0x3C000000u : 0u);
        uint32_t p1 = (a.z ? 0x3C00u : 0u) | (a.w ? 0x3C000000u : 0u);
        *(uint2*)(base + swz((uint32_t)row, (uint32_t)(c4 * 8))) = make_uint2(p0, p1);
    }
}
__device__ __forceinline__ void g_cpB(uint32_t smaddr, int ch, int tid) {
    size_t kk = (size_t)ch * KC;
    #pragma unroll
    for (int p = 0; p < 8; p++) {
        int lin = p * 256 + tid;
        int row = lin >> 3, cx = lin & 7;
        const void* src = g_Bh + (size_t)row * NROWS + kk + cx * 8;
        cp_async16(smaddr + swz((uint32_t)row, (uint32_t)(cx * 16)), src);
    }
}

__global__ void __launch_bounds__(256, 2) gat_gemm_kernel(const int* __restrict__ adj,
                                                          float* __restrict__ out) {
    extern __shared__ char sm[];
    uint32_t smb = smem_to_u32(sm);
    int tid = threadIdx.x;
    int l = tid & 31, w = tid >> 5;
    int mw = w & 1, nw = w >> 1;          // 2 x 4 warps, warp tile 32x64
    int c = blockIdx.x;                   // 0..295

    // static unit range: 272 CTAs x 7 units + 24 CTAs x 6 units = 2048
    int start, cnt;
    if (c < 272) { start = 7 * c; cnt = 7; }
    else         { start = 1904 + 6 * (c - 272); cnt = 6; }

    int g = l >> 3, lr = l & 7;
    uint32_t a_row0 = (uint32_t)(mw * 32 + (g & 1) * 8 + lr);
    uint32_t a_kb   = (uint32_t)((g >> 1) * 16);
    uint32_t b_row0 = (uint32_t)(nw * 64 + (g >> 1) * 8 + lr);
    uint32_t b_kb   = (uint32_t)((g & 1) * 16);

    while (cnt > 0) {
        int mt = start >> 4, kt = start & 15;
        int take = 16 - kt; if (take > cnt) take = cnt;
        start += take; cnt -= take;

        int m0 = mt * 64;
        int ch0 = kt * 8;                 // first chunk (KC=64 each)
        int NCHUNK = take * 8;            // 8..56 chunks

        float acc[2][8][4];
        #pragma unroll
        for (int mf = 0; mf < 2; mf++)
            #pragma unroll
            for (int nf = 0; nf < 8; nf++)
                #pragma unroll
                for (int q = 0; q < 4; q++) acc[mf][nf][q] = 0.0f;

        AReg ar;
        __syncthreads();   // protect smem stages from previous segment's readers
        g_ldgA(ar, adj, m0, ch0 + 0, tid); g_stsA(ar, sm + 0 * A_ST, tid);
        g_ldgA(ar, adj, m0, ch0 + 1, tid); g_stsA(ar, sm + 1 * A_ST, tid);
        g_ldgA(ar, adj, m0, ch0 + 2, tid);
        g_cpB(smb + B_BASE, ch0, tid);
        cp_commit();

        for (int it = 0; it < NCHUNK; ++it) {
            cp_wait<0>();
            __syncthreads();
            if (it + 1 < NCHUNK) {
                g_cpB(smb + B_BASE + ((it + 1) & 1) * B_ST, ch0 + it + 1, tid);
                cp_commit();
            }
            if (it + 2 < NCHUNK) {
                g_stsA(ar, sm + ((it + 2) % 3) * A_ST, tid);
                if (it + 3 < NCHUNK) g_ldgA(ar, adj, m0, ch0 + it + 3, tid);
            }

            uint32_t Ab = smb + (it % 3) * A_ST;
            uint32_t Bb = smb + B_BASE + (it & 1) * B_ST;
            #pragma unroll
            for (int ks = 0; ks < 4; ks++) {
                uint32_t af[2][4];
                #pragma unroll
                for (int mf = 0; mf < 2; mf++) {
                    uint32_t o = swz(a_row0 + mf * 16u, (uint32_t)(ks * 32) + a_kb);
                    ldsm_x4(Ab + o, af[mf][0], af[mf][1], af[mf][2], af[mf][3]);
                }
                #pragma unroll
                for (int nf2 = 0; nf2 < 4; nf2++) {
                    uint32_t r0, r1, r2, r3;
                    uint32_t o = swz(b_row0 + nf2 * 16u, (uint32_t)(ks * 32) + b_kb);
                    ldsm_x4(Bb + o, r0, r1, r2, r3);
                    #pragma unroll
                    for (int mf = 0; mf < 2; mf++) {
                        mma_f16(acc[mf][nf2 * 2 + 0], af[mf], r0, r1);
                        mma_f16(acc[mf][nf2 * 2 + 1], af[mf], r2, r3);
                    }
                }
            }
        }

        // flush segment: out += 9e15 * partial (out prefilled with NEG*S)
        #pragma unroll
        for (int mf = 0; mf < 2; mf++) {
            int r0 = m0 + mw * 32 + mf * 16 + (l >> 2);
            #pragma unroll
            for (int nf = 0; nf < 8; nf++) {
                int col = nw * 64 + nf * 8 + (l & 3) * 2;
                atomicAdd(out + (size_t)r0 * OUT_F + col,       -NEGC * acc[mf][nf][0]);
                atomicAdd(out + (size_t)r0 * OUT_F + col + 1,   -NEGC * acc[mf][nf][1]);
                atomicAdd(out + (size_t)(r0 + 8) * OUT_F + col,     -NEGC * acc[mf][nf][2]);
                atomicAdd(out + (size_t)(r0 + 8) * OUT_F + col + 1, -NEGC * acc[mf][nf][3]);
            }
        }
    }
}

// ---------------------------------------------------------------------------
// Launch
// ---------------------------------------------------------------------------
extern "C" void kernel_launch(void* const* d_in, const int* in_sizes, int n_in,
                              void* d_out, int out_size) {
    const float* x   = (const float*)d_in[0];   // [8192, 512]
    const float* W   = (const float*)d_in[1];   // [512, 256]
    const int*   adj = (const int*)d_in[3];     // [8192, 8192]
    float* out = (float*)d_out;                 // [8192, 256]

    convert_W_kernel<<<512, 256>>>(W);

    cudaFuncSetAttribute(gemm_h_kernel, cudaFuncAttributeMaxDynamicSharedMemorySize, H_SMEM);
    gemm_h_kernel<<<dim3(2, 64), 256, H_SMEM>>>(x);

    prefill_out_kernel<<<128, 256>>>(out);

    cudaFuncSetAttribute(gat_gemm_kernel, cudaFuncAttributeMaxDynamicSharedMemorySize, GAT_SMEM);
    gat_gemm_kernel<<<296, 256, GAT_SMEM>>>(adj, out);
}

// round 15
// speedup vs baseline: 1.2102x; 1.0247x over previous
#include <cuda_runtime.h>
#include <cuda_fp16.h>
#include <cstdint>

// ---------------------------------------------------------------------------
// GAT layer. N=8192, IN_F=512, OUT_F=256.
// out = NEG * (colsum(h) - (adj>0) @ h),  h = x @ W, NEG = -9e15.
// R15: GAT kernel FROZEN (R14: balanced 296-CTA schedule, 124.8us).
// gemm_h cut to 2 limb-terms (xh*Wh + xh*Wl) + occ2; prefill rebalanced.
// 4 launches: convert_W, gemm_h, prefill_out, gat.
// ---------------------------------------------------------------------------

#define NROWS   8192
#define IN_F    512
#define OUT_F   256
#define NEGC    (-9.0e15f)

// Static scratch
__device__ unsigned short g_Bh[(size_t)OUT_F * NROWS];   // h^T fp16 [k][j]
__device__ unsigned short g_W16[2 * OUT_F * IN_F];       // W^T fp16 limbs [limb][n][k]
__device__ float          g_Sp[64 * OUT_F];              // per-j-tile colsum partials

// ---------------------------------------------------------------------------
// helpers
// ---------------------------------------------------------------------------
__device__ __forceinline__ uint32_t smem_to_u32(const void* p) {
    uint32_t a;
    asm("{ .reg .u64 t; cvta.to.shared.u64 t, %1; cvt.u32.u64 %0, t; }" : "=r"(a) : "l"(p));
    return a;
}
__device__ __forceinline__ void cp_async16(uint32_t dst, const void* src) {
    asm volatile("cp.async.cg.shared.global [%0], [%1], 16;" :: "r"(dst), "l"(src));
}
__device__ __forceinline__ void cp_commit() { asm volatile("cp.async.commit_group;"); }
template <int N>
__device__ __forceinline__ void cp_wait() { asm volatile("cp.async.wait_group %0;" :: "n"(N)); }

__device__ __forceinline__ void ldsm_x4(uint32_t addr, uint32_t& r0, uint32_t& r1,
                                        uint32_t& r2, uint32_t& r3) {
    asm volatile("ldmatrix.sync.aligned.m8n8.x4.shared.b16 {%0,%1,%2,%3}, [%4];"
                 : "=r"(r0), "=r"(r1), "=r"(r2), "=r"(r3) : "r"(addr));
}
__device__ __forceinline__ void mma_f16(float* c, const uint32_t* a, uint32_t b0, uint32_t b1) {
    asm volatile("mma.sync.aligned.m16n8k16.row.col.f32.f16.f16.f32 "
                 "{%0,%1,%2,%3}, {%4,%5,%6,%7}, {%8,%9}, {%0,%1,%2,%3};"
                 : "+f"(c[0]), "+f"(c[1]), "+f"(c[2]), "+f"(c[3])
                 : "r"(a[0]), "r"(a[1]), "r"(a[2]), "r"(a[3]), "r"(b0), "r"(b1));
}
__device__ __forceinline__ uint32_t swz(uint32_t row, uint32_t col) {
    return row * 128u + (col ^ ((row & 7u) * 16u));
}
__device__ __forceinline__ uint32_t packh(float a, float b) {
    return (uint32_t)__half_as_ushort(__float2half_rn(a)) |
           ((uint32_t)__half_as_ushort(__float2half_rn(b)) << 16);
}

// ---------------------------------------------------------------------------
// Kernel A: split W into fp16 hi/lo limbs, transposed: g_W16[limb][n][k]
// ---------------------------------------------------------------------------
__global__ void __launch_bounds__(256) convert_W_kernel(const float* __restrict__ W) {
    int idx = blockIdx.x * 256 + threadIdx.x;       // 131072 total
    int n = idx & 255, k = idx >> 8;
    float v = W[(size_t)k * OUT_F + n];
    __half hi = __float2half_rn(v);
    __half lo = __float2half_rn(v - __half2float(hi));
    g_W16[n * IN_F + k] = __half_as_ushort(hi);
    g_W16[OUT_F * IN_F + n * IN_F + k] = __half_as_ushort(lo);
}

// ---------------------------------------------------------------------------
// Kernel B: h = x @ W on tensor cores, 2 terms: fp16(x)*(Whi + Wlo).
// CTA: 128 j-rows x 128 n-cols, K=512 (8 chunks of 64). Grid (2 nt, 64 jt).
// Stages: Ah(16K)|Bh(16K)|Bl(16K) = 48KB x2 -> 96KB, occ 2.
// Emits g_Bh[k][j] fp16 and g_Sp[jt][k] colsum partials.
// ---------------------------------------------------------------------------
#define HKC   64
#define H_A   (128 * HKC * 2)   // 16 KB per tile
#define H_STG (3 * H_A)         // Ah|Bh|Bl = 48 KB
#define H_SMEM (2 * H_STG)      // 96 KB

struct XReg { float4 v[8]; };

__device__ __forceinline__ void h_loadx(XReg& xr, const float* __restrict__ x,
                                        int j0, int it, int tid) {
    #pragma unroll
    for (int p = 0; p < 8; p++) {
        int lin = p * 256 + tid;
        int row = lin >> 4, c4 = lin & 15;
        xr.v[p] = *(const float4*)(x + (size_t)(j0 + row) * IN_F + it * HKC + c4 * 4);
    }
}
__device__ __forceinline__ void h_stsx(const XReg& xr, char* stg, int tid) {
    #pragma unroll
    for (int p = 0; p < 8; p++) {
        int lin = p * 256 + tid;
        int row = lin >> 4, c4 = lin & 15;
        float4 v = xr.v[p];
        uint32_t o = swz((uint32_t)row, (uint32_t)(c4 * 8));
        *(uint2*)(stg + o) = make_uint2(packh(v.x, v.y), packh(v.z, v.w));
    }
}
__device__ __forceinline__ void h_cpB(uint32_t stg, int n0, int it, int tid) {
    #pragma unroll
    for (int limb = 0; limb < 2; limb++) {
        #pragma unroll
        for (int p = 0; p < 4; p++) {
            int lin = p * 256 + tid;
            int row = lin >> 3, cx = lin & 7;
            const void* src = g_W16 + (size_t)limb * OUT_F * IN_F +
                              (size_t)(n0 + row) * IN_F + it * HKC + cx * 8;
            cp_async16(stg + H_A + limb * H_A + swz((uint32_t)row, (uint32_t)(cx * 16)), src);
        }
    }
}

__global__ void __launch_bounds__(256, 2) gemm_h_kernel(const float* __restrict__ x) {
    extern __shared__ char sm[];
    uint32_t smb = smem_to_u32(sm);
    int tid = threadIdx.x;
    int l = tid & 31, w = tid >> 5;
    int mw = w & 3, nw = w >> 2;          // 4 x 2 warps, warp tile 32x64
    int n0 = blockIdx.x * 128;
    int j0 = blockIdx.y * 128;
    int jt = blockIdx.y;

    int g = l >> 3, lr = l & 7;
    uint32_t a_row0 = (uint32_t)(mw * 32 + (g & 1) * 8 + lr);
    uint32_t a_kb   = (uint32_t)((g >> 1) * 16);
    uint32_t b_row0 = (uint32_t)(nw * 64 + (g >> 1) * 8 + lr);
    uint32_t b_kb   = (uint32_t)((g & 1) * 16);

    float acc[2][8][4];
    #pragma unroll
    for (int mf = 0; mf < 2; mf++)
        #pragma unroll
        for (int nf = 0; nf < 8; nf++)
            #pragma unroll
            for (int q = 0; q < 4; q++) acc[mf][nf][q] = 0.0f;

    XReg xr;
    h_loadx(xr, x, j0, 0, tid);
    h_stsx(xr, sm, tid);
    h_cpB(smb, n0, 0, tid);
    cp_commit();
    h_loadx(xr, x, j0, 1, tid);

    for (int it = 0; it < 8; ++it) {
        cp_wait<0>();
        __syncthreads();
        if (it + 1 < 8) {
            char* stg = sm + ((it + 1) & 1) * H_STG;
            h_stsx(xr, stg, tid);
            h_cpB(smb + ((it + 1) & 1) * H_STG, n0, it + 1, tid);
            cp_commit();
            if (it + 2 < 8) h_loadx(xr, x, j0, it + 2, tid);
        }
        uint32_t Sb = smb + (it & 1) * H_STG;
        #pragma unroll
        for (int ks = 0; ks < 4; ks++) {
            uint32_t afh[2][4];
            #pragma unroll
            for (int mf = 0; mf < 2; mf++) {
                uint32_t o = swz(a_row0 + mf * 16u, (uint32_t)(ks * 32) + a_kb);
                ldsm_x4(Sb + o, afh[mf][0], afh[mf][1], afh[mf][2], afh[mf][3]);
            }
            #pragma unroll
            for (int nf2 = 0; nf2 < 4; nf2++) {
                uint32_t o = swz(b_row0 + nf2 * 16u, (uint32_t)(ks * 32) + b_kb);
                uint32_t h0, h1, h2, h3, l0, l1, l2, l3;
                ldsm_x4(Sb + H_A + o, h0, h1, h2, h3);
                ldsm_x4(Sb + 2 * H_A + o, l0, l1, l2, l3);
                #pragma unroll
                for (int mf = 0; mf < 2; mf++) {
                    mma_f16(acc[mf][nf2 * 2 + 0], afh[mf], h0, h1);
                    mma_f16(acc[mf][nf2 * 2 + 1], afh[mf], h2, h3);
                    mma_f16(acc[mf][nf2 * 2 + 0], afh[mf], l0, l1);
                    mma_f16(acc[mf][nf2 * 2 + 1], afh[mf], l2, l3);
                }
            }
        }
    }

    // epilogue: stage h (fp16) into smem [j][k], pitch 130 halves
    __syncthreads();
    unsigned short* hbuf = (unsigned short*)sm;
    const int P = 130;
    #pragma unroll
    for (int mf = 0; mf < 2; mf++) {
        int r = mw * 32 + mf * 16 + (l >> 2);
        #pragma unroll
        for (int nf = 0; nf < 8; nf++) {
            int c = nw * 64 + nf * 8 + (l & 3) * 2;
            *(uint32_t*)&hbuf[r * P + c] = packh(acc[mf][nf][0], acc[mf][nf][1]);
            *(uint32_t*)&hbuf[(r + 8) * P + c] = packh(acc[mf][nf][2], acc[mf][nf][3]);
        }
    }
    __syncthreads();

    // colsum partials
    if (tid < 128) {
        float s = 0.0f;
        #pragma unroll 8
        for (int j = 0; j < 128; j++)
            s += __half2float(__ushort_as_half(hbuf[j * P + tid]));
        g_Sp[jt * OUT_F + n0 + tid] = s;
    }

    // transposed write: g_Bh[n0+kl][j0 .. j0+127]
    {
        int kl = tid >> 1, jh = (tid & 1) * 64;
        unsigned short* dst = g_Bh + (size_t)(n0 + kl) * NROWS + j0 + jh;
        #pragma unroll
        for (int q = 0; q < 8; q++) {
            uint32_t u[4];
            #pragma unroll
            for (int e = 0; e < 4; e++) {
                unsigned short v0 = hbuf[(jh + q * 8 + e * 2 + 0) * P + kl];
                unsigned short v1 = hbuf[(jh + q * 8 + e * 2 + 1) * P + kl];
                u[e] = (uint32_t)v0 | ((uint32_t)v1 << 16);
            }
            *(uint4*)(dst + q * 8) = make_uint4(u[0], u[1], u[2], u[3]);
        }
    }
}

// ---------------------------------------------------------------------------
// Kernel C: fused colsum-reduce + prefill: out[r][c] = NEG * S[c]
// Grid 256 blocks; block b reduces g_Sp then fills rows [32b, 32b+32).
// ---------------------------------------------------------------------------
__global__ void __launch_bounds__(256) prefill_out_kernel(float* __restrict__ out) {
    __shared__ float sS[256];
    int t = threadIdx.x;
    float s = 0.0f;
    #pragma unroll 8
    for (int jt = 0; jt < 64; jt++) s += g_Sp[jt * OUT_F + t];
    sS[t] = NEGC * s;
    __syncthreads();
    float v = sS[t];
    float* base = out + (size_t)blockIdx.x * 32 * OUT_F + t;
    #pragma unroll 8
    for (int r = 0; r < 32; r++) base[r * OUT_F] = v;
}

// ---------------------------------------------------------------------------
// Kernel D (FROZEN, R14): masked GEMM (adj>0) @ h. Statically load-balanced
// grid=296 (=148 SMs x occ2): 2048 units (128 mt x 16 kt, K=512 each),
// CTA c owns a contiguous range (<=2 mt segments); per segment run the R7
// mainloop over its contiguous chunks, flush via atomicAdd into prefilled out.
// A ring 3 stages (8KB, reg-staged 3 ahead), B ring 2 stages (32KB cp.async)
// -> 88KB, 2 CTAs/SM. 8 warps = 2mw x 4nw, warp tile 32x64.
// ---------------------------------------------------------------------------
#define KC     64
#define A_ST   (64 * KC * 2)              // 8 KB
#define B_ST   (256 * KC * 2)             // 32 KB
#define B_BASE (3 * A_ST)                 // 24 KB
#define GAT_SMEM (B_BASE + 2 * B_ST)      // 88 KB

struct AReg { int4 v[4]; };

__device__ __forceinline__ void g_ldgA(AReg& ar, const int* __restrict__ adj,
                                       int m0, int ch, int tid) {
    size_t kk = (size_t)ch * KC;
    #pragma unroll
    for (int p = 0; p < 4; p++) {
        int lin = p * 256 + tid;
        int row = lin >> 4, c4 = lin & 15;
        ar.v[p] = *(const int4*)(adj + (size_t)(m0 + row) * NROWS + kk + c4 * 4);
    }
}
__device__ __forceinline__ void g_stsA(const AReg& ar, char* base, int tid) {
    #pragma unroll
    for (int p = 0; p < 4; p++) {
        int lin = p * 256 + tid;
        int row = lin >> 4, c4 = lin & 15;
        int4 a = ar.v[p];
        uint32_t p0 = (a.x ? 0x3C00u : 0u) | (a.y ? 0x3C000000u : 0u);
        uint32_t p1 = (a.z ? 0x3C00u : 0u) | (a.w ? 0x3C000000u : 0u);
        *(uint2*)(base + swz((uint32_t)row, (uint32_t)(c4 * 8))) = make_uint2(p0, p1);
    }
}
__device__ __forceinline__ void g_cpB(uint32_t smaddr, int ch, int tid) {
    size_t kk = (size_t)ch * KC;
    #pragma unroll
    for (int p = 0; p < 8; p++) {
        int lin = p * 256 + tid;
        int row = lin >> 3, cx = lin & 7;
        const void* src = g_Bh + (size_t)row * NROWS + kk + cx * 8;
        cp_async16(smaddr + swz((uint32_t)row, (uint32_t)(cx * 16)), src);
    }
}

__global__ void __launch_bounds__(256, 2) gat_gemm_kernel(const int* __restrict__ adj,
                                                          float* __restrict__ out) {
    extern __shared__ char sm[];
    uint32_t smb = smem_to_u32(sm);
    int tid = threadIdx.x;
    int l = tid & 31, w = tid >> 5;
    int mw = w & 1, nw = w >> 1;          // 2 x 4 warps, warp tile 32x64
    int c = blockIdx.x;                   // 0..295

    // static unit range: 272 CTAs x 7 units + 24 CTAs x 6 units = 2048
    int start, cnt;
    if (c < 272) { start = 7 * c; cnt = 7; }
    else         { start = 1904 + 6 * (c - 272); cnt = 6; }

    int g = l >> 3, lr = l & 7;
    uint32_t a_row0 = (uint32_t)(mw * 32 + (g & 1) * 8 + lr);
    uint32_t a_kb   = (uint32_t)((g >> 1) * 16);
    uint32_t b_row0 = (uint32_t)(nw * 64 + (g >> 1) * 8 + lr);
    uint32_t b_kb   = (uint32_t)((g & 1) * 16);

    while (cnt > 0) {
        int mt = start >> 4, kt = start & 15;
        int take = 16 - kt; if (take > cnt) take = cnt;
        start += take; cnt -= take;

        int m0 = mt * 64;
        int ch0 = kt * 8;                 // first chunk (KC=64 each)
        int NCHUNK = take * 8;            // 8..56 chunks

        float acc[2][8][4];
        #pragma unroll
        for (int mf = 0; mf < 2; mf++)
            #pragma unroll
            for (int nf = 0; nf < 8; nf++)
                #pragma unroll
                for (int q = 0; q < 4; q++) acc[mf][nf][q] = 0.0f;

        AReg ar;
        __syncthreads();   // protect smem stages from previous segment's readers
        g_ldgA(ar, adj, m0, ch0 + 0, tid); g_stsA(ar, sm + 0 * A_ST, tid);
        g_ldgA(ar, adj, m0, ch0 + 1, tid); g_stsA(ar, sm + 1 * A_ST, tid);
        g_ldgA(ar, adj, m0, ch0 + 2, tid);
        g_cpB(smb + B_BASE, ch0, tid);
        cp_commit();

        for (int it = 0; it < NCHUNK; ++it) {
            cp_wait<0>();
            __syncthreads();
            if (it + 1 < NCHUNK) {
                g_cpB(smb + B_BASE + ((it + 1) & 1) * B_ST, ch0 + it + 1, tid);
                cp_commit();
            }
            if (it + 2 < NCHUNK) {
                g_stsA(ar, sm + ((it + 2) % 3) * A_ST, tid);
                if (it + 3 < NCHUNK) g_ldgA(ar, adj, m0, ch0 + it + 3, tid);
            }

            uint32_t Ab = smb + (it % 3) * A_ST;
            uint32_t Bb = smb + B_BASE + (it & 1) * B_ST;
            #pragma unroll
            for (int ks = 0; ks < 4; ks++) {
                uint32_t af[2][4];
                #pragma unroll
                for (int mf = 0; mf < 2; mf++) {
                    uint32_t o = swz(a_row0 + mf * 16u, (uint32_t)(ks * 32) + a_kb);
                    ldsm_x4(Ab + o, af[mf][0], af[mf][1], af[mf][2], af[mf][3]);
                }
                #pragma unroll
                for (int nf2 = 0; nf2 < 4; nf2++) {
                    uint32_t r0, r1, r2, r3;
                    uint32_t o = swz(b_row0 + nf2 * 16u, (uint32_t)(ks * 32) + b_kb);
                    ldsm_x4(Bb + o, r0, r1, r2, r3);
                    #pragma unroll
                    for (int mf = 0; mf < 2; mf++) {
                        mma_f16(acc[mf][nf2 * 2 + 0], af[mf], r0, r1);
                        mma_f16(acc[mf][nf2 * 2 + 1], af[mf], r2, r3);
                    }
                }
            }
        }

        // flush segment: out += 9e15 * partial (out prefilled with NEG*S)
        #pragma unroll
        for (int mf = 0; mf < 2; mf++) {
            int r0 = m0 + mw * 32 + mf * 16 + (l >> 2);
            #pragma unroll
            for (int nf = 0; nf < 8; nf++) {
                int col = nw * 64 + nf * 8 + (l & 3) * 2;
                atomicAdd(out + (size_t)r0 * OUT_F + col,       -NEGC * acc[mf][nf][0]);
                atomicAdd(out + (size_t)r0 * OUT_F + col + 1,   -NEGC * acc[mf][nf][1]);
                atomicAdd(out + (size_t)(r0 + 8) * OUT_F + col,     -NEGC * acc[mf][nf][2]);
                atomicAdd(out + (size_t)(r0 + 8) * OUT_F + col + 1, -NEGC * acc[mf][nf][3]);
            }
        }
    }
}

// ---------------------------------------------------------------------------
// Launch
// ---------------------------------------------------------------------------
extern "C" void kernel_launch(void* const* d_in, const int* in_sizes, int n_in,
                              void* d_out, int out_size) {
    const float* x   = (const float*)d_in[0];   // [8192, 512]
    const float* W   = (const float*)d_in[1];   // [512, 256]
    const int*   adj = (const int*)d_in[3];     // [8192, 8192]
    float* out = (float*)d_out;                 // [8192, 256]

    convert_W_kernel<<<512, 256>>>(W);

    cudaFuncSetAttribute(gemm_h_kernel, cudaFuncAttributeMaxDynamicSharedMemorySize, H_SMEM);
    gemm_h_kernel<<<dim3(2, 64), 256, H_SMEM>>>(x);

    prefill_out_kernel<<<256, 256>>>(out);

    cudaFuncSetAttribute(gat_gemm_kernel, cudaFuncAttributeMaxDynamicSharedMemorySize, GAT_SMEM);
    gat_gemm_kernel<<<296, 256, GAT_SMEM>>>(adj, out);
}